// round 11
// baseline (speedup 1.0000x reference)
#include <cuda_runtime.h>

#define BB 256
#define NSTEP 32
#define NIMG (NSTEP*BB)   // 8192

#define NWARP 21
#define NTHREAD (NWARP*32)            // 672
#define NBLOCK ((NIMG + NWARP - 1) / NWARP)   // 391

#define OUT_GUARD 81920
#define OUT_STATE (81920 + 49152)

__device__ float g_Mt[600];              // transposed transition matrices: g_Mt[j*60+t] = M[t][j]
__device__ float g_T[BB * NSTEP * 6];    // b-major guard copy: g_T[b*192 + n*6 + r]

// ---------------- smem layout (floats) for cnn kernel ----------------
#define OFF_W1P 0       // 8*12 {w0..w8,pad3}
#define OFF_B1  96      // 8
#define OFF_W2P 104     // 128*12 (16B aligned: 104*4=416)
#define OFF_B2  1640    // 16
#define OFF_W3  1656    // 32*145
#define OFF_B3  6296    // 32
#define OFF_WD  6328    // 10*33
#define OFF_BD  6658    // 10
#define OFF_WB  6672    // per-warp buffers (6672*4 % 16 == 0)
#define WBSTRIDE 2248
#define SMEM_FLOATS (OFF_WB + NWARP*WBSTRIDE)   // 53880 floats = 215520 B

// packed fp32x2 FMA (sm_103a)
__device__ __forceinline__ float2 ffma2(float2 a, float2 b, float2 c) {
    unsigned long long A = *reinterpret_cast<unsigned long long*>(&a);
    unsigned long long Bv = *reinterpret_cast<unsigned long long*>(&b);
    unsigned long long C = *reinterpret_cast<unsigned long long*>(&c);
    unsigned long long D;
    asm("fma.rn.f32x2 %0, %1, %2, %3;" : "=l"(D) : "l"(A), "l"(Bv), "l"(C));
    return *reinterpret_cast<float2*>(&D);
}

__global__ __launch_bounds__(NTHREAD, 1) void cnn_kernel(
    const float* __restrict__ seq,
    const float* __restrict__ w1, const float* __restrict__ b1,
    const float* __restrict__ w2, const float* __restrict__ b2,
    const float* __restrict__ w3, const float* __restrict__ b3,
    const float* __restrict__ wd, const float* __restrict__ bd,
    const float* __restrict__ trans,
    float* __restrict__ out)
{
    extern __shared__ float sm[];
    const int tid = threadIdx.x;
    const int warp = tid >> 5;
    const int lane = tid & 31;

    // ---- block 0: compute transition matrices once, write transposed to global ----
    if (blockIdx.x == 0 && tid < 60) {
        int r = tid / 10, i = tid - r * 10;
        float row[10];
        if (i == 9) {
            #pragma unroll
            for (int j = 0; j < 10; j++) row[j] = (j == 9) ? 1.f : 0.f;
        } else {
            const float* src = trans + (size_t)(r * 9 + i) * 10;
            float m = -1e30f;
            #pragma unroll
            for (int j = 0; j < 10; j++) { row[j] = src[j] * 10.0f; m = fmaxf(m, row[j]); }
            float s = 0.f;
            #pragma unroll
            for (int j = 0; j < 10; j++) { row[j] = __expf(row[j] - m); s += row[j]; }
            float inv = 1.0f / s;
            #pragma unroll
            for (int j = 0; j < 10; j++) row[j] *= inv;
        }
        #pragma unroll
        for (int j = 0; j < 10; j++) g_Mt[j * 60 + r * 10 + i] = row[j];
    }

    // ---- cooperative weight staging (w1/w2 row-padded to 12 for vector loads) ----
    for (int i = tid; i < 96; i += NTHREAD) {
        int c = i / 12, k = i - c * 12;
        sm[OFF_W1P + i] = (k < 9) ? w1[c * 9 + k] : 0.f;
    }
    for (int i = tid; i < 1536; i += NTHREAD) {
        int f = i / 12, k = i - f * 12;
        sm[OFF_W2P + i] = (k < 9) ? w2[f * 9 + k] : 0.f;
    }
    for (int i = tid; i < 4608; i += NTHREAD) {
        int oc = i / 144, r = i - oc * 144;
        sm[OFF_W3 + oc * 145 + r] = w3[i];
    }
    for (int i = tid; i < 320; i += NTHREAD) {
        int d = i >> 5, c = i & 31;
        sm[OFF_WD + d * 33 + c] = wd[i];
    }
    if (tid < 8)  sm[OFF_B1 + tid] = b1[tid];
    if (tid < 16) sm[OFF_B2 + tid] = b2[tid];
    if (tid < 32) sm[OFF_B3 + tid] = b3[tid];
    if (tid < 10) sm[OFF_BD + tid] = bd[tid];
    __syncthreads();

    // ---- per-warp image ----
    const int img = blockIdx.x * NWARP + warp;
    if (img >= NIMG) return;              // only after the single block barrier
    const int b = img & 255;
    const int n = img >> 8;
    float* wb   = sm + OFF_WB + warp * WBSTRIDE;
    float* sin_ = wb;            // 784 (dead after stage1)
    float* p1   = wb + 784;      // 8 x 13 x 14
    float* p2   = wb;            // 16 x 5 x 6, overlays sin
    float* scr  = wb + 480;      // 32 v + 10 probs

    {
        const float4* in4 = (const float4*)(seq + (size_t)(b * 32 + n) * 784);
        float4* s4 = (float4*)sin_;
        for (int i = lane; i < 196; i += 32) s4[i] = in4[i];
    }
    __syncwarp();

    // ---- stage 1: conv1(1->8) + relu + pool -> p1 ----
    for (int pos = lane; pos < 169; pos += 32) {
        int py = pos / 13, px = pos - py * 13;
        const float* base = sin_ + (py * 56 + px * 2);
        float2 ra[4], rb[4], mi[4];
        #pragma unroll
        for (int r = 0; r < 4; r++) {
            ra[r] = *(const float2*)(base + r * 28);
            rb[r] = *(const float2*)(base + r * 28 + 2);
            mi[r] = make_float2(ra[r].y, rb[r].x);
        }
        #pragma unroll
        for (int c = 0; c < 8; c++) {
            const float* wp = sm + OFF_W1P + c * 12;
            float4 qa = *(const float4*)wp;
            float4 qb = *(const float4*)(wp + 4);
            float w[9] = {qa.x, qa.y, qa.z, qa.w, qb.x, qb.y, qb.z, qb.w, wp[8]};
            float bias = sm[OFF_B1 + c];
            float2 at = make_float2(bias, bias);
            float2 ab = at;
            #pragma unroll
            for (int ky = 0; ky < 3; ky++) {
                float w0 = w[ky * 3 + 0], w1v = w[ky * 3 + 1], w2v = w[ky * 3 + 2];
                at = ffma2(ra[ky], make_float2(w0, w0), at);
                at = ffma2(mi[ky], make_float2(w1v, w1v), at);
                at = ffma2(rb[ky], make_float2(w2v, w2v), at);
                ab = ffma2(ra[ky + 1], make_float2(w0, w0), ab);
                ab = ffma2(mi[ky + 1], make_float2(w1v, w1v), ab);
                ab = ffma2(rb[ky + 1], make_float2(w2v, w2v), ab);
            }
            p1[c * 182 + py * 14 + px] =
                0.25f * (fmaxf(at.x, 0.f) + fmaxf(at.y, 0.f) +
                         fmaxf(ab.x, 0.f) + fmaxf(ab.y, 0.f));
        }
    }
    __syncwarp();

    // ---- stage 2: conv2(8->16) + relu + pool -> p2 ----
    if (lane < 25) {
        int py = lane / 5, px = lane - py * 5;
        #pragma unroll
        for (int ocb = 0; ocb < 2; ocb++) {
            float2 at[8], ab[8];
            #pragma unroll
            for (int o = 0; o < 8; o++) {
                float bias = sm[OFF_B2 + ocb * 8 + o];
                at[o] = make_float2(bias, bias);
                ab[o] = at[o];
            }
            for (int ic = 0; ic < 8; ic++) {
                const float* pin = p1 + ic * 182 + py * 28 + px * 2;
                float2 ra[4], rb[4], mi[4];
                #pragma unroll
                for (int r = 0; r < 4; r++) {
                    ra[r] = *(const float2*)(pin + r * 14);
                    rb[r] = *(const float2*)(pin + r * 14 + 2);
                    mi[r] = make_float2(ra[r].y, rb[r].x);
                }
                #pragma unroll
                for (int o = 0; o < 8; o++) {
                    const float* wp = sm + OFF_W2P + ((ocb * 8 + o) * 8 + ic) * 12;
                    float4 qa = *(const float4*)wp;
                    float4 qb = *(const float4*)(wp + 4);
                    float w[9] = {qa.x, qa.y, qa.z, qa.w, qb.x, qb.y, qb.z, qb.w, wp[8]};
                    #pragma unroll
                    for (int ky = 0; ky < 3; ky++) {
                        float w0 = w[ky * 3 + 0], w1v = w[ky * 3 + 1], w2v = w[ky * 3 + 2];
                        at[o] = ffma2(ra[ky], make_float2(w0, w0), at[o]);
                        at[o] = ffma2(mi[ky], make_float2(w1v, w1v), at[o]);
                        at[o] = ffma2(rb[ky], make_float2(w2v, w2v), at[o]);
                        ab[o] = ffma2(ra[ky + 1], make_float2(w0, w0), ab[o]);
                        ab[o] = ffma2(mi[ky + 1], make_float2(w1v, w1v), ab[o]);
                        ab[o] = ffma2(rb[ky + 1], make_float2(w2v, w2v), ab[o]);
                    }
                }
            }
            #pragma unroll
            for (int o = 0; o < 8; o++)
                p2[(ocb * 8 + o) * 30 + py * 6 + px] =
                    0.25f * (fmaxf(at[o].x, 0.f) + fmaxf(at[o].y, 0.f) +
                             fmaxf(ab[o].x, 0.f) + fmaxf(ab[o].y, 0.f));
        }
    }
    __syncwarp();

    // ---- stage 3: conv3(16->32) + relu + pool -> v (lane = oc) ----
    float v;
    {
        float bias = sm[OFF_B3 + lane];
        float2 at = make_float2(bias, bias);
        float2 ab = at;
        const float* w = sm + OFF_W3 + lane * 145;
        for (int ic = 0; ic < 16; ic++) {
            const float* pin = p2 + ic * 30;
            float2 ra[4], rb[4], mi[4];
            #pragma unroll
            for (int r = 0; r < 4; r++) {
                ra[r] = *(const float2*)(pin + r * 6);
                rb[r] = *(const float2*)(pin + r * 6 + 2);
                mi[r] = make_float2(ra[r].y, rb[r].x);
            }
            const float* wi = w + ic * 9;
            #pragma unroll
            for (int ky = 0; ky < 3; ky++) {
                float w0 = wi[ky * 3 + 0], w1v = wi[ky * 3 + 1], w2v = wi[ky * 3 + 2];
                at = ffma2(ra[ky], make_float2(w0, w0), at);
                at = ffma2(mi[ky], make_float2(w1v, w1v), at);
                at = ffma2(rb[ky], make_float2(w2v, w2v), at);
                ab = ffma2(ra[ky + 1], make_float2(w0, w0), ab);
                ab = ffma2(mi[ky + 1], make_float2(w1v, w1v), ab);
                ab = ffma2(rb[ky + 1], make_float2(w2v, w2v), ab);
            }
        }
        v = 0.25f * (fmaxf(at.x, 0.f) + fmaxf(at.y, 0.f) +
                     fmaxf(ab.x, 0.f) + fmaxf(ab.y, 0.f));
    }
    scr[lane] = v;
    __syncwarp();

    // ---- stage 4: dense + softmax + guards ----
    float logit = 0.f;
    if (lane < 10) {
        logit = sm[OFF_BD + lane];
        const float* w = sm + OFF_WD + lane * 33;
        #pragma unroll
        for (int c = 0; c < 32; c++) logit += scr[c] * w[c];
    }
    float lm = (lane < 10) ? logit : -1e30f;
    #pragma unroll
    for (int o = 16; o > 0; o >>= 1) lm = fmaxf(lm, __shfl_xor_sync(0xffffffffu, lm, o));
    float e = (lane < 10) ? __expf(logit - lm) : 0.f;
    float s = e;
    #pragma unroll
    for (int o = 16; o > 0; o >>= 1) s += __shfl_xor_sync(0xffffffffu, s, o);
    float prob = e / s;
    if (lane < 10) {
        out[(size_t)img * 10 + lane] = prob;
        scr[32 + lane] = prob;
    }
    __syncwarp();
    if (lane < 6) {
        const float* p = scr + 32;
        float g;
        if      (lane == 0) g = p[8];
        else if (lane == 1) g = p[4] + p[6];
        else if (lane == 2) g = p[0] + p[2];
        else if (lane == 3) g = p[7] + p[9];
        else if (lane == 4) g = p[5];
        else                g = p[1] + p[3];
        out[OUT_GUARD + (size_t)img * 6 + lane] = g;
        g_T[b * (NSTEP * 6) + n * 6 + lane] = g;   // b-major copy for the scan
    }
}

// ---------------- scan: one 32-thread block per batch element, barrier-free ----------------
__global__ __launch_bounds__(32) void scan_kernel(float* __restrict__ out_state)
{
    __shared__ float g[NSTEP * 6];

    const int lane = threadIdx.x;
    const int b = blockIdx.x;

    // guard prefetch: 768 contiguous bytes = 6 lines, 48x LDG.128
    {
        const float4* src = (const float4*)(g_T + b * (NSTEP * 6));
        float4* dst = (float4*)g;
        dst[lane] = src[lane];
        if (lane < 16) dst[32 + lane] = src[32 + lane];
    }

    // lane j loads its 60-float column slice (contiguous, 15x LDG.128)
    float Mc[60];
    const int j = (lane < 10) ? lane : 0;
    {
        const float4* src = (const float4*)(g_Mt + j * 60);
        #pragma unroll
        for (int q = 0; q < 15; q++) {
            float4 vv = src[q];
            Mc[4 * q + 0] = vv.x; Mc[4 * q + 1] = vv.y;
            Mc[4 * q + 2] = vv.z; Mc[4 * q + 3] = vv.w;
        }
    }
    __syncwarp();

    float st = (lane == 0) ? 1.f : 0.f;
    #pragma unroll 8
    for (int nn = 0; nn < NSTEP; nn++) {
        const float* gn = g + nn * 6;
        float g0 = gn[0], g1 = gn[1], g2 = gn[2], g3 = gn[3], g4 = gn[4], g5 = gn[5];
        float a[10];
        #pragma unroll
        for (int i = 0; i < 10; i++)
            a[i] = g0 * Mc[i] + g1 * Mc[10 + i] + g2 * Mc[20 + i]
                 + g3 * Mc[30 + i] + g4 * Mc[40 + i] + g5 * Mc[50 + i];
        float ns = 0.f;
        #pragma unroll
        for (int i = 0; i < 10; i++)
            ns += __shfl_sync(0xffffffffu, st, i) * a[i];
        st = ns;
    }
    if (lane < 10) out_state[b * 10 + lane] = st;
}

extern "C" void kernel_launch(void* const* d_in, const int* in_sizes, int n_in,
                              void* d_out, int out_size)
{
    const float* seq = (const float*)d_in[0];
    const float* w1  = (const float*)d_in[1];
    const float* b1  = (const float*)d_in[2];
    const float* w2  = (const float*)d_in[3];
    const float* b2  = (const float*)d_in[4];
    const float* w3  = (const float*)d_in[5];
    const float* b3  = (const float*)d_in[6];
    const float* wd  = (const float*)d_in[7];
    const float* bd  = (const float*)d_in[8];
    const float* tr  = (const float*)d_in[9];
    float* out = (float*)d_out;

    static int smem_set = 0;
    if (!smem_set) {
        cudaFuncSetAttribute(cnn_kernel, cudaFuncAttributeMaxDynamicSharedMemorySize,
                             SMEM_FLOATS * sizeof(float));
        smem_set = 1;
    }
    cnn_kernel<<<NBLOCK, NTHREAD, SMEM_FLOATS * sizeof(float)>>>(
        seq, w1, b1, w2, b2, w3, b3, wd, bd, tr, out);
    scan_kernel<<<BB, 32>>>(out + OUT_STATE);
}

// round 12
// speedup vs baseline: 1.4591x; 1.4591x over previous
#include <cuda_runtime.h>

#define BB 256
#define NSTEP 32
#define NIMG (NSTEP*BB)   // 8192

#define NWARP 10
#define NTHREAD (NWARP*32)                    // 320
#define NBLOCK ((NIMG + NWARP - 1) / NWARP)   // 820

#define OUT_GUARD 81920
#define OUT_STATE (81920 + 49152)

__device__ float g_Mt[600];              // transposed transition matrices
__device__ float g_T[BB * NSTEP * 6];    // b-major guard copy

// uniform-access weights -> constant memory (LDCU broadcast path)
__constant__ float c_w1[72];
__constant__ float c_b1[8];
__constant__ float c_w2[1152];
__constant__ float c_b2[16];

// ---------------- smem layout (floats): only lane-indexed tables + warp buffers ----
#define OFF_W3  0       // 32*145
#define OFF_B3  4640    // 32
#define OFF_WD  4672    // 10*33
#define OFF_BD  5002    // 10
#define OFF_WB  5012    // per-warp buffers (5012*4 % 16 == 0)
#define WBSTRIDE 2248
#define SMEM_FLOATS (OFF_WB + NWARP*WBSTRIDE)   // 27492 floats = 109968 B

// packed fp32x2 FMA (sm_103a)
__device__ __forceinline__ float2 ffma2(float2 a, float2 b, float2 c) {
    unsigned long long A = *reinterpret_cast<unsigned long long*>(&a);
    unsigned long long Bv = *reinterpret_cast<unsigned long long*>(&b);
    unsigned long long C = *reinterpret_cast<unsigned long long*>(&c);
    unsigned long long D;
    asm("fma.rn.f32x2 %0, %1, %2, %3;" : "=l"(D) : "l"(A), "l"(Bv), "l"(C));
    return *reinterpret_cast<float2*>(&D);
}

__global__ __launch_bounds__(NTHREAD, 2) void cnn_kernel(
    const float* __restrict__ seq,
    const float* __restrict__ w3, const float* __restrict__ b3,
    const float* __restrict__ wd, const float* __restrict__ bd,
    const float* __restrict__ trans,
    float* __restrict__ out)
{
    extern __shared__ float sm[];
    const int tid = threadIdx.x;
    const int warp = tid >> 5;
    const int lane = tid & 31;

    // ---- block 0: transition matrices once, transposed to global ----
    if (blockIdx.x == 0 && tid < 60) {
        int r = tid / 10, i = tid - r * 10;
        float row[10];
        if (i == 9) {
            #pragma unroll
            for (int j = 0; j < 10; j++) row[j] = (j == 9) ? 1.f : 0.f;
        } else {
            const float* src = trans + (size_t)(r * 9 + i) * 10;
            float m = -1e30f;
            #pragma unroll
            for (int j = 0; j < 10; j++) { row[j] = src[j] * 10.0f; m = fmaxf(m, row[j]); }
            float s = 0.f;
            #pragma unroll
            for (int j = 0; j < 10; j++) { row[j] = __expf(row[j] - m); s += row[j]; }
            float inv = 1.0f / s;
            #pragma unroll
            for (int j = 0; j < 10; j++) row[j] *= inv;
        }
        #pragma unroll
        for (int j = 0; j < 10; j++) g_Mt[j * 60 + r * 10 + i] = row[j];
    }

    // ---- stage lane-indexed tables into smem ----
    for (int i = tid; i < 4608; i += NTHREAD) {
        int oc = i / 144, r = i - oc * 144;
        sm[OFF_W3 + oc * 145 + r] = w3[i];
    }
    for (int i = tid; i < 320; i += NTHREAD) {
        int d = i >> 5, c = i & 31;
        sm[OFF_WD + d * 33 + c] = wd[i];
    }
    if (tid < 32) sm[OFF_B3 + tid] = b3[tid];
    if (tid < 10) sm[OFF_BD + tid] = bd[tid];
    __syncthreads();

    // ---- per-warp image ----
    const int img = blockIdx.x * NWARP + warp;
    if (img >= NIMG) return;              // after the single block barrier
    const int b = img & 255;
    const int n = img >> 8;
    float* wb   = sm + OFF_WB + warp * WBSTRIDE;
    float* sin_ = wb;            // 784 (dead after stage1)
    float* p1   = wb + 784;      // 8 x 13 x 14
    float* p2   = wb;            // 16 x 5 x 6, overlays sin
    float* scr  = wb + 480;      // 32 v + 10 probs

    {
        const float4* in4 = (const float4*)(seq + (size_t)(b * 32 + n) * 784);
        float4* s4 = (float4*)sin_;
        for (int i = lane; i < 196; i += 32) s4[i] = in4[i];
    }
    __syncwarp();

    // ---- stage 1: conv1(1->8) + relu + pool -> p1 (weights: constant/LDCU) ----
    for (int pos = lane; pos < 169; pos += 32) {
        int py = pos / 13, px = pos - py * 13;
        const float* base = sin_ + (py * 56 + px * 2);
        float2 ra[4], rb[4], mi[4];
        #pragma unroll
        for (int r = 0; r < 4; r++) {
            ra[r] = *(const float2*)(base + r * 28);
            rb[r] = *(const float2*)(base + r * 28 + 2);
            mi[r] = make_float2(ra[r].y, rb[r].x);
        }
        #pragma unroll
        for (int c = 0; c < 8; c++) {
            float bias = c_b1[c];
            float2 at = make_float2(bias, bias);
            float2 ab = at;
            #pragma unroll
            for (int ky = 0; ky < 3; ky++) {
                float w0 = c_w1[c * 9 + ky * 3 + 0];
                float w1v = c_w1[c * 9 + ky * 3 + 1];
                float w2v = c_w1[c * 9 + ky * 3 + 2];
                at = ffma2(ra[ky], make_float2(w0, w0), at);
                at = ffma2(mi[ky], make_float2(w1v, w1v), at);
                at = ffma2(rb[ky], make_float2(w2v, w2v), at);
                ab = ffma2(ra[ky + 1], make_float2(w0, w0), ab);
                ab = ffma2(mi[ky + 1], make_float2(w1v, w1v), ab);
                ab = ffma2(rb[ky + 1], make_float2(w2v, w2v), ab);
            }
            p1[c * 182 + py * 14 + px] =
                0.25f * (fmaxf(at.x, 0.f) + fmaxf(at.y, 0.f) +
                         fmaxf(ab.x, 0.f) + fmaxf(ab.y, 0.f));
        }
    }
    __syncwarp();

    // ---- stage 2: conv2(8->16) + relu + pool -> p2 (weights: constant/LDCU) ----
    if (lane < 25) {
        int py = lane / 5, px = lane - py * 5;
        #pragma unroll
        for (int ocb = 0; ocb < 2; ocb++) {
            float2 at[8], ab[8];
            #pragma unroll
            for (int o = 0; o < 8; o++) {
                float bias = c_b2[ocb * 8 + o];
                at[o] = make_float2(bias, bias);
                ab[o] = at[o];
            }
            for (int ic = 0; ic < 8; ic++) {
                const float* pin = p1 + ic * 182 + py * 28 + px * 2;
                float2 ra[4], rb[4], mi[4];
                #pragma unroll
                for (int r = 0; r < 4; r++) {
                    ra[r] = *(const float2*)(pin + r * 14);
                    rb[r] = *(const float2*)(pin + r * 14 + 2);
                    mi[r] = make_float2(ra[r].y, rb[r].x);
                }
                #pragma unroll
                for (int o = 0; o < 8; o++) {
                    const int wbase = ((ocb * 8 + o) * 8 + ic) * 9;
                    #pragma unroll
                    for (int ky = 0; ky < 3; ky++) {
                        float w0 = c_w2[wbase + ky * 3 + 0];
                        float w1v = c_w2[wbase + ky * 3 + 1];
                        float w2v = c_w2[wbase + ky * 3 + 2];
                        at[o] = ffma2(ra[ky], make_float2(w0, w0), at[o]);
                        at[o] = ffma2(mi[ky], make_float2(w1v, w1v), at[o]);
                        at[o] = ffma2(rb[ky], make_float2(w2v, w2v), at[o]);
                        ab[o] = ffma2(ra[ky + 1], make_float2(w0, w0), ab[o]);
                        ab[o] = ffma2(mi[ky + 1], make_float2(w1v, w1v), ab[o]);
                        ab[o] = ffma2(rb[ky + 1], make_float2(w2v, w2v), ab[o]);
                    }
                }
            }
            #pragma unroll
            for (int o = 0; o < 8; o++)
                p2[(ocb * 8 + o) * 30 + py * 6 + px] =
                    0.25f * (fmaxf(at[o].x, 0.f) + fmaxf(at[o].y, 0.f) +
                             fmaxf(ab[o].x, 0.f) + fmaxf(ab[o].y, 0.f));
        }
    }
    __syncwarp();

    // ---- stage 3: conv3(16->32) + relu + pool -> v (lane = oc; w3 in smem) ----
    float v;
    {
        float bias = sm[OFF_B3 + lane];
        float2 at = make_float2(bias, bias);
        float2 ab = at;
        const float* w = sm + OFF_W3 + lane * 145;
        for (int ic = 0; ic < 16; ic++) {
            const float* pin = p2 + ic * 30;
            float2 ra[4], rb[4], mi[4];
            #pragma unroll
            for (int r = 0; r < 4; r++) {
                ra[r] = *(const float2*)(pin + r * 6);
                rb[r] = *(const float2*)(pin + r * 6 + 2);
                mi[r] = make_float2(ra[r].y, rb[r].x);
            }
            const float* wi = w + ic * 9;
            #pragma unroll
            for (int ky = 0; ky < 3; ky++) {
                float w0 = wi[ky * 3 + 0], w1v = wi[ky * 3 + 1], w2v = wi[ky * 3 + 2];
                at = ffma2(ra[ky], make_float2(w0, w0), at);
                at = ffma2(mi[ky], make_float2(w1v, w1v), at);
                at = ffma2(rb[ky], make_float2(w2v, w2v), at);
                ab = ffma2(ra[ky + 1], make_float2(w0, w0), ab);
                ab = ffma2(mi[ky + 1], make_float2(w1v, w1v), ab);
                ab = ffma2(rb[ky + 1], make_float2(w2v, w2v), ab);
            }
        }
        v = 0.25f * (fmaxf(at.x, 0.f) + fmaxf(at.y, 0.f) +
                     fmaxf(ab.x, 0.f) + fmaxf(ab.y, 0.f));
    }
    scr[lane] = v;
    __syncwarp();

    // ---- stage 4: dense + softmax + guards ----
    float logit = 0.f;
    if (lane < 10) {
        logit = sm[OFF_BD + lane];
        const float* w = sm + OFF_WD + lane * 33;
        #pragma unroll
        for (int c = 0; c < 32; c++) logit += scr[c] * w[c];
    }
    float lm = (lane < 10) ? logit : -1e30f;
    #pragma unroll
    for (int o = 16; o > 0; o >>= 1) lm = fmaxf(lm, __shfl_xor_sync(0xffffffffu, lm, o));
    float e = (lane < 10) ? __expf(logit - lm) : 0.f;
    float s = e;
    #pragma unroll
    for (int o = 16; o > 0; o >>= 1) s += __shfl_xor_sync(0xffffffffu, s, o);
    float prob = e / s;
    if (lane < 10) {
        out[(size_t)img * 10 + lane] = prob;
        scr[32 + lane] = prob;
    }
    __syncwarp();
    if (lane < 6) {
        const float* p = scr + 32;
        float g;
        if      (lane == 0) g = p[8];
        else if (lane == 1) g = p[4] + p[6];
        else if (lane == 2) g = p[0] + p[2];
        else if (lane == 3) g = p[7] + p[9];
        else if (lane == 4) g = p[5];
        else                g = p[1] + p[3];
        out[OUT_GUARD + (size_t)img * 6 + lane] = g;
        g_T[b * (NSTEP * 6) + n * 6 + lane] = g;
    }
}

// ---------------- scan: one 32-thread block per batch element, barrier-free ----------------
__global__ __launch_bounds__(32) void scan_kernel(float* __restrict__ out_state)
{
    __shared__ float g[NSTEP * 6];

    const int lane = threadIdx.x;
    const int b = blockIdx.x;

    {
        const float4* src = (const float4*)(g_T + b * (NSTEP * 6));
        float4* dst = (float4*)g;
        dst[lane] = src[lane];
        if (lane < 16) dst[32 + lane] = src[32 + lane];
    }

    float Mc[60];
    const int j = (lane < 10) ? lane : 0;
    {
        const float4* src = (const float4*)(g_Mt + j * 60);
        #pragma unroll
        for (int q = 0; q < 15; q++) {
            float4 vv = src[q];
            Mc[4 * q + 0] = vv.x; Mc[4 * q + 1] = vv.y;
            Mc[4 * q + 2] = vv.z; Mc[4 * q + 3] = vv.w;
        }
    }
    __syncwarp();

    float st = (lane == 0) ? 1.f : 0.f;
    #pragma unroll 8
    for (int nn = 0; nn < NSTEP; nn++) {
        const float* gn = g + nn * 6;
        float g0 = gn[0], g1 = gn[1], g2 = gn[2], g3 = gn[3], g4 = gn[4], g5 = gn[5];
        float a[10];
        #pragma unroll
        for (int i = 0; i < 10; i++)
            a[i] = g0 * Mc[i] + g1 * Mc[10 + i] + g2 * Mc[20 + i]
                 + g3 * Mc[30 + i] + g4 * Mc[40 + i] + g5 * Mc[50 + i];
        float ns = 0.f;
        #pragma unroll
        for (int i = 0; i < 10; i++)
            ns += __shfl_sync(0xffffffffu, st, i) * a[i];
        st = ns;
    }
    if (lane < 10) out_state[b * 10 + lane] = st;
}

extern "C" void kernel_launch(void* const* d_in, const int* in_sizes, int n_in,
                              void* d_out, int out_size)
{
    const float* seq = (const float*)d_in[0];
    const float* w1  = (const float*)d_in[1];
    const float* b1  = (const float*)d_in[2];
    const float* w2  = (const float*)d_in[3];
    const float* b2  = (const float*)d_in[4];
    const float* w3  = (const float*)d_in[5];
    const float* b3  = (const float*)d_in[6];
    const float* wd  = (const float*)d_in[7];
    const float* bd  = (const float*)d_in[8];
    const float* tr  = (const float*)d_in[9];
    float* out = (float*)d_out;

    static int smem_set = 0;
    if (!smem_set) {
        cudaFuncSetAttribute(cnn_kernel, cudaFuncAttributeMaxDynamicSharedMemorySize,
                             SMEM_FLOATS * sizeof(float));
        smem_set = 1;
    }

    // uniform weights -> constant memory (async D2D, graph-capturable)
    cudaMemcpyToSymbolAsync(c_w1, w1, 72 * sizeof(float), 0, cudaMemcpyDeviceToDevice);
    cudaMemcpyToSymbolAsync(c_b1, b1, 8 * sizeof(float), 0, cudaMemcpyDeviceToDevice);
    cudaMemcpyToSymbolAsync(c_w2, w2, 1152 * sizeof(float), 0, cudaMemcpyDeviceToDevice);
    cudaMemcpyToSymbolAsync(c_b2, b2, 16 * sizeof(float), 0, cudaMemcpyDeviceToDevice);

    cnn_kernel<<<NBLOCK, NTHREAD, SMEM_FLOATS * sizeof(float)>>>(
        seq, w3, b3, wd, bd, tr, out);
    scan_kernel<<<BB, 32>>>(out + OUT_STATE);
}

// round 13
// speedup vs baseline: 1.4974x; 1.0263x over previous
#include <cuda_runtime.h>

#define BB 256
#define NSTEP 32
#define NIMG (NSTEP*BB)   // 8192

#define NWARP 10
#define NTHREAD (NWARP*32)                    // 320
#define NBLOCK ((NIMG + NWARP - 1) / NWARP)   // 820

#define OUT_GUARD 81920
#define OUT_STATE (81920 + 49152)

__device__ float g_Mt[600];              // transposed transition matrices
__device__ float g_T[BB * NSTEP * 6];    // b-major guard copy
__device__ float g_stage[1248];          // packed staging for the constant block

// one packed constant block: [w1 72 | b1 8 | w2 1152 | b2 16]
#define CW1 0
#define CB1 72
#define CW2 80
#define CB2 1232
__constant__ float c_wb[1248];

// ---------------- smem layout (floats): lane-indexed tables + warp buffers ----
#define OFF_W3  0       // 32*145
#define OFF_B3  4640    // 32
#define OFF_WD  4672    // 10*33
#define OFF_BD  5002    // 10
#define OFF_WB  5012    // per-warp buffers (5012*4 % 16 == 0)
#define WBSTRIDE 2248
#define SMEM_FLOATS (OFF_WB + NWARP*WBSTRIDE)   // 27492 floats = 109968 B

// packed fp32x2 FMA (sm_103a)
__device__ __forceinline__ float2 ffma2(float2 a, float2 b, float2 c) {
    unsigned long long A = *reinterpret_cast<unsigned long long*>(&a);
    unsigned long long Bv = *reinterpret_cast<unsigned long long*>(&b);
    unsigned long long C = *reinterpret_cast<unsigned long long*>(&c);
    unsigned long long D;
    asm("fma.rn.f32x2 %0, %1, %2, %3;" : "=l"(D) : "l"(A), "l"(Bv), "l"(C));
    return *reinterpret_cast<float2*>(&D);
}

// ---------------- prep: pack constants + compute transition matrices ----------------
__global__ __launch_bounds__(256) void prep_kernel(
    const float* __restrict__ w1, const float* __restrict__ b1,
    const float* __restrict__ w2, const float* __restrict__ b2,
    const float* __restrict__ trans)
{
    const int tid = threadIdx.x;
    for (int i = tid; i < 72; i += 256)   g_stage[CW1 + i] = w1[i];
    if (tid < 8)                          g_stage[CB1 + tid] = b1[tid];
    for (int i = tid; i < 1152; i += 256) g_stage[CW2 + i] = w2[i];
    if (tid < 16)                         g_stage[CB2 + tid] = b2[tid];

    if (tid < 60) {
        int r = tid / 10, i = tid - r * 10;
        float row[10];
        if (i == 9) {
            #pragma unroll
            for (int j = 0; j < 10; j++) row[j] = (j == 9) ? 1.f : 0.f;
        } else {
            const float* src = trans + (size_t)(r * 9 + i) * 10;
            float m = -1e30f;
            #pragma unroll
            for (int j = 0; j < 10; j++) { row[j] = src[j] * 10.0f; m = fmaxf(m, row[j]); }
            float s = 0.f;
            #pragma unroll
            for (int j = 0; j < 10; j++) { row[j] = __expf(row[j] - m); s += row[j]; }
            float inv = 1.0f / s;
            #pragma unroll
            for (int j = 0; j < 10; j++) row[j] *= inv;
        }
        #pragma unroll
        for (int j = 0; j < 10; j++) g_Mt[j * 60 + r * 10 + i] = row[j];
    }
}

__global__ __launch_bounds__(NTHREAD, 2) void cnn_kernel(
    const float* __restrict__ seq,
    const float* __restrict__ w3, const float* __restrict__ b3,
    const float* __restrict__ wd, const float* __restrict__ bd,
    float* __restrict__ out)
{
    extern __shared__ float sm[];
    const int tid = threadIdx.x;
    const int warp = tid >> 5;
    const int lane = tid & 31;

    // ---- stage lane-indexed tables into smem ----
    for (int i = tid; i < 4608; i += NTHREAD) {
        int oc = i / 144, r = i - oc * 144;
        sm[OFF_W3 + oc * 145 + r] = w3[i];
    }
    for (int i = tid; i < 320; i += NTHREAD) {
        int d = i >> 5, c = i & 31;
        sm[OFF_WD + d * 33 + c] = wd[i];
    }
    if (tid < 32) sm[OFF_B3 + tid] = b3[tid];
    if (tid < 10) sm[OFF_BD + tid] = bd[tid];
    __syncthreads();

    // ---- per-warp image ----
    const int img = blockIdx.x * NWARP + warp;
    if (img >= NIMG) return;              // after the single block barrier
    const int b = img & 255;
    const int n = img >> 8;
    float* wb   = sm + OFF_WB + warp * WBSTRIDE;
    float* sin_ = wb;            // 784 (dead after stage1)
    float* p1   = wb + 784;      // 8 x 13 x 14
    float* p2   = wb;            // 16 x 5 x 6, overlays sin
    float* scr  = wb + 480;      // 32 v + 10 probs

    {
        const float4* in4 = (const float4*)(seq + (size_t)(b * 32 + n) * 784);
        float4* s4 = (float4*)sin_;
        for (int i = lane; i < 196; i += 32) s4[i] = in4[i];
    }
    __syncwarp();

    // ---- stage 1: conv1(1->8) + relu + pool -> p1 (weights: constant) ----
    for (int pos = lane; pos < 169; pos += 32) {
        int py = pos / 13, px = pos - py * 13;
        const float* base = sin_ + (py * 56 + px * 2);
        float2 ra[4], rb[4], mi[4];
        #pragma unroll
        for (int r = 0; r < 4; r++) {
            ra[r] = *(const float2*)(base + r * 28);
            rb[r] = *(const float2*)(base + r * 28 + 2);
            mi[r] = make_float2(ra[r].y, rb[r].x);
        }
        #pragma unroll
        for (int c = 0; c < 8; c++) {
            float bias = c_wb[CB1 + c];
            float2 at = make_float2(bias, bias);
            float2 ab = at;
            #pragma unroll
            for (int ky = 0; ky < 3; ky++) {
                float w0 = c_wb[CW1 + c * 9 + ky * 3 + 0];
                float w1v = c_wb[CW1 + c * 9 + ky * 3 + 1];
                float w2v = c_wb[CW1 + c * 9 + ky * 3 + 2];
                at = ffma2(ra[ky], make_float2(w0, w0), at);
                at = ffma2(mi[ky], make_float2(w1v, w1v), at);
                at = ffma2(rb[ky], make_float2(w2v, w2v), at);
                ab = ffma2(ra[ky + 1], make_float2(w0, w0), ab);
                ab = ffma2(mi[ky + 1], make_float2(w1v, w1v), ab);
                ab = ffma2(rb[ky + 1], make_float2(w2v, w2v), ab);
            }
            p1[c * 182 + py * 14 + px] =
                0.25f * (fmaxf(at.x, 0.f) + fmaxf(at.y, 0.f) +
                         fmaxf(ab.x, 0.f) + fmaxf(ab.y, 0.f));
        }
    }
    __syncwarp();

    // ---- stage 2: conv2(8->16) + relu + pool -> p2 (weights: constant) ----
    if (lane < 25) {
        int py = lane / 5, px = lane - py * 5;
        #pragma unroll
        for (int ocb = 0; ocb < 2; ocb++) {
            float2 at[8], ab[8];
            #pragma unroll
            for (int o = 0; o < 8; o++) {
                float bias = c_wb[CB2 + ocb * 8 + o];
                at[o] = make_float2(bias, bias);
                ab[o] = at[o];
            }
            for (int ic = 0; ic < 8; ic++) {
                const float* pin = p1 + ic * 182 + py * 28 + px * 2;
                float2 ra[4], rb[4], mi[4];
                #pragma unroll
                for (int r = 0; r < 4; r++) {
                    ra[r] = *(const float2*)(pin + r * 14);
                    rb[r] = *(const float2*)(pin + r * 14 + 2);
                    mi[r] = make_float2(ra[r].y, rb[r].x);
                }
                #pragma unroll
                for (int o = 0; o < 8; o++) {
                    const int wbase = CW2 + ((ocb * 8 + o) * 8 + ic) * 9;
                    #pragma unroll
                    for (int ky = 0; ky < 3; ky++) {
                        float w0 = c_wb[wbase + ky * 3 + 0];
                        float w1v = c_wb[wbase + ky * 3 + 1];
                        float w2v = c_wb[wbase + ky * 3 + 2];
                        at[o] = ffma2(ra[ky], make_float2(w0, w0), at[o]);
                        at[o] = ffma2(mi[ky], make_float2(w1v, w1v), at[o]);
                        at[o] = ffma2(rb[ky], make_float2(w2v, w2v), at[o]);
                        ab[o] = ffma2(ra[ky + 1], make_float2(w0, w0), ab[o]);
                        ab[o] = ffma2(mi[ky + 1], make_float2(w1v, w1v), ab[o]);
                        ab[o] = ffma2(rb[ky + 1], make_float2(w2v, w2v), ab[o]);
                    }
                }
            }
            #pragma unroll
            for (int o = 0; o < 8; o++)
                p2[(ocb * 8 + o) * 30 + py * 6 + px] =
                    0.25f * (fmaxf(at[o].x, 0.f) + fmaxf(at[o].y, 0.f) +
                             fmaxf(ab[o].x, 0.f) + fmaxf(ab[o].y, 0.f));
        }
    }
    __syncwarp();

    // ---- stage 3: conv3(16->32) + relu + pool -> v (lane = oc; w3 in smem) ----
    float v;
    {
        float bias = sm[OFF_B3 + lane];
        float2 at = make_float2(bias, bias);
        float2 ab = at;
        const float* w = sm + OFF_W3 + lane * 145;
        for (int ic = 0; ic < 16; ic++) {
            const float* pin = p2 + ic * 30;
            float2 ra[4], rb[4], mi[4];
            #pragma unroll
            for (int r = 0; r < 4; r++) {
                ra[r] = *(const float2*)(pin + r * 6);
                rb[r] = *(const float2*)(pin + r * 6 + 2);
                mi[r] = make_float2(ra[r].y, rb[r].x);
            }
            const float* wi = w + ic * 9;
            #pragma unroll
            for (int ky = 0; ky < 3; ky++) {
                float w0 = wi[ky * 3 + 0], w1v = wi[ky * 3 + 1], w2v = wi[ky * 3 + 2];
                at = ffma2(ra[ky], make_float2(w0, w0), at);
                at = ffma2(mi[ky], make_float2(w1v, w1v), at);
                at = ffma2(rb[ky], make_float2(w2v, w2v), at);
                ab = ffma2(ra[ky + 1], make_float2(w0, w0), ab);
                ab = ffma2(mi[ky + 1], make_float2(w1v, w1v), ab);
                ab = ffma2(rb[ky + 1], make_float2(w2v, w2v), ab);
            }
        }
        v = 0.25f * (fmaxf(at.x, 0.f) + fmaxf(at.y, 0.f) +
                     fmaxf(ab.x, 0.f) + fmaxf(ab.y, 0.f));
    }
    scr[lane] = v;
    __syncwarp();

    // ---- stage 4: dense + softmax + guards ----
    float logit = 0.f;
    if (lane < 10) {
        logit = sm[OFF_BD + lane];
        const float* w = sm + OFF_WD + lane * 33;
        #pragma unroll
        for (int c = 0; c < 32; c++) logit += scr[c] * w[c];
    }
    float lm = (lane < 10) ? logit : -1e30f;
    #pragma unroll
    for (int o = 16; o > 0; o >>= 1) lm = fmaxf(lm, __shfl_xor_sync(0xffffffffu, lm, o));
    float e = (lane < 10) ? __expf(logit - lm) : 0.f;
    float s = e;
    #pragma unroll
    for (int o = 16; o > 0; o >>= 1) s += __shfl_xor_sync(0xffffffffu, s, o);
    float prob = e / s;
    if (lane < 10) {
        out[(size_t)img * 10 + lane] = prob;
        scr[32 + lane] = prob;
    }
    __syncwarp();
    if (lane < 6) {
        const float* p = scr + 32;
        float g;
        if      (lane == 0) g = p[8];
        else if (lane == 1) g = p[4] + p[6];
        else if (lane == 2) g = p[0] + p[2];
        else if (lane == 3) g = p[7] + p[9];
        else if (lane == 4) g = p[5];
        else                g = p[1] + p[3];
        out[OUT_GUARD + (size_t)img * 6 + lane] = g;
        g_T[b * (NSTEP * 6) + n * 6 + lane] = g;
    }
}

// ---------------- scan: one 32-thread block per batch element, barrier-free ----------------
__global__ __launch_bounds__(32) void scan_kernel(float* __restrict__ out_state)
{
    __shared__ float g[NSTEP * 6];

    const int lane = threadIdx.x;
    const int b = blockIdx.x;

    {
        const float4* src = (const float4*)(g_T + b * (NSTEP * 6));
        float4* dst = (float4*)g;
        dst[lane] = src[lane];
        if (lane < 16) dst[32 + lane] = src[32 + lane];
    }

    float Mc[60];
    const int j = (lane < 10) ? lane : 0;
    {
        const float4* src = (const float4*)(g_Mt + j * 60);
        #pragma unroll
        for (int q = 0; q < 15; q++) {
            float4 vv = src[q];
            Mc[4 * q + 0] = vv.x; Mc[4 * q + 1] = vv.y;
            Mc[4 * q + 2] = vv.z; Mc[4 * q + 3] = vv.w;
        }
    }
    __syncwarp();

    float st = (lane == 0) ? 1.f : 0.f;
    #pragma unroll 8
    for (int nn = 0; nn < NSTEP; nn++) {
        const float* gn = g + nn * 6;
        float g0 = gn[0], g1 = gn[1], g2 = gn[2], g3 = gn[3], g4 = gn[4], g5 = gn[5];
        float a[10];
        #pragma unroll
        for (int i = 0; i < 10; i++)
            a[i] = g0 * Mc[i] + g1 * Mc[10 + i] + g2 * Mc[20 + i]
                 + g3 * Mc[30 + i] + g4 * Mc[40 + i] + g5 * Mc[50 + i];
        float ns = 0.f;
        #pragma unroll
        for (int i = 0; i < 10; i++)
            ns += __shfl_sync(0xffffffffu, st, i) * a[i];
        st = ns;
    }
    if (lane < 10) out_state[b * 10 + lane] = st;
}

extern "C" void kernel_launch(void* const* d_in, const int* in_sizes, int n_in,
                              void* d_out, int out_size)
{
    const float* seq = (const float*)d_in[0];
    const float* w1  = (const float*)d_in[1];
    const float* b1  = (const float*)d_in[2];
    const float* w2  = (const float*)d_in[3];
    const float* b2  = (const float*)d_in[4];
    const float* w3  = (const float*)d_in[5];
    const float* b3  = (const float*)d_in[6];
    const float* wd  = (const float*)d_in[7];
    const float* bd  = (const float*)d_in[8];
    const float* tr  = (const float*)d_in[9];
    float* out = (float*)d_out;

    static int smem_set = 0;
    if (!smem_set) {
        cudaFuncSetAttribute(cnn_kernel, cudaFuncAttributeMaxDynamicSharedMemorySize,
                             SMEM_FLOATS * sizeof(float));
        smem_set = 1;
    }

    prep_kernel<<<1, 256>>>(w1, b1, w2, b2, tr);

    // one packed constant update (async D2D from staging, graph-capturable)
    static float* stage_ptr = nullptr;
    if (!stage_ptr) cudaGetSymbolAddress((void**)&stage_ptr, g_stage);
    cudaMemcpyToSymbolAsync(c_wb, stage_ptr, 1248 * sizeof(float), 0,
                            cudaMemcpyDeviceToDevice);

    cnn_kernel<<<NBLOCK, NTHREAD, SMEM_FLOATS * sizeof(float)>>>(
        seq, w3, b3, wd, bd, out);
    scan_kernel<<<BB, 32>>>(out + OUT_STATE);
}